// round 1
// baseline (speedup 1.0000x reference)
#include <cuda_runtime.h>
#include <cuda_bf16.h>

// ---------------- Model constants ----------------
#define BATCH 2
#define NTOK 4096           // 4095 tokens + cls
#define NIN 4095
#define LIN 1024
#define DIM 512
#define HEADS 8
#define DH 64
#define BH (BATCH*HEADS)    // 16
#define LM 256              // landmarks
#define GRP 16              // tokens per landmark (4096/256)
#define OUTC 1000

// ---------------- Scratch (device globals; no allocation allowed) ----------------
__device__ float g_h   [BATCH*NTOK*DIM];       // running hidden  [2,4096,512]
__device__ float g_xn  [BATCH*NTOK*DIM];       // LN output / merged-head temp
__device__ float g_qkv [BATCH*NTOK*3*DIM];     // [2,4096,1536]
__device__ float g_q   [BH*NTOK*DH];
__device__ float g_k   [BH*NTOK*DH];
__device__ float g_v   [BH*NTOK*DH];
__device__ float g_ql  [BH*LM*DH];
__device__ float g_kl  [BH*LM*DH];
__device__ float g_s1  [BH*NTOK*LM];           // attn1 [16,4096,256]
__device__ float g_s2  [BH*LM*LM];             // attn2 [16,256,256]
__device__ float g_s3  [BH*LM*NTOK];           // attn3 [16,256,4096]
__device__ float g_za  [BH*LM*LM];
__device__ float g_zb  [BH*LM*LM];
__device__ float g_xz  [BH*LM*LM];
__device__ float g_t1  [BH*LM*LM];
__device__ float g_t2  [BH*LM*LM];
__device__ float g_av  [BH*LM*DH];
__device__ float g_zav [BH*LM*DH];
__device__ float g_ao  [BH*NTOK*DH];           // attention output head-major
__device__ float g_clsn[BATCH*DIM];
__device__ float g_scal[2];                    // pinv col/row norm maxima

// ---------------- Generic tiled SGEMM ----------------
// C = alpha * A @ op(B)  (+ diagAdd*I) (+ bias) (+ residual) (relu)
// A: [M,K] row-major. B: transB ? [N,K] : [K,N]. C: [M,N]. Batched via blockIdx.z.
#define F_TRANSB 1
#define F_RELU   2
#define F_BIAS   4
#define F_RES    8
#define F_DIAG   16

__global__ __launch_bounds__(256) void gemm_kernel(
    const float* __restrict__ A, const float* __restrict__ B, float* __restrict__ C,
    const float* __restrict__ bias, const float* __restrict__ res,
    int M, int N, int K,
    long long sA, long long sB, long long sC,
    int flags, float alpha, float diagAdd)
{
    const bool transB = flags & F_TRANSB;
    int bz = blockIdx.z;
    A += bz * sA; B += bz * sB; C += bz * sC;
    const float* resp = (flags & F_RES) ? res + bz * sC : nullptr;

    __shared__ float As[16][68];
    __shared__ float Bs[16][68];

    int tid = threadIdx.x;
    int tx = tid & 15, ty = tid >> 4;
    int rowBase = blockIdx.y * 64;
    int colBase = blockIdx.x * 64;

    float acc[4][4] = {};

    for (int k0 = 0; k0 < K; k0 += 16) {
        #pragma unroll
        for (int i = 0; i < 4; i++) {
            int idx = tid + i * 256;
            int m = idx >> 4;
            int kk = idx & 15;
            int r = rowBase + m;
            As[kk][m] = (r < M) ? A[(long long)r * K + k0 + kk] : 0.f;
        }
        if (!transB) {
            #pragma unroll
            for (int i = 0; i < 4; i++) {
                int idx = tid + i * 256;
                int n = idx & 63;
                int kk = idx >> 6;
                int c = colBase + n;
                Bs[kk][n] = (c < N) ? B[(long long)(k0 + kk) * N + c] : 0.f;
            }
        } else {
            #pragma unroll
            for (int i = 0; i < 4; i++) {
                int idx = tid + i * 256;
                int n = idx >> 4;
                int kk = idx & 15;
                int c = colBase + n;
                Bs[kk][n] = (c < N) ? B[(long long)c * K + k0 + kk] : 0.f;
            }
        }
        __syncthreads();
        #pragma unroll
        for (int kk = 0; kk < 16; kk++) {
            float4 a4 = *(const float4*)&As[kk][ty * 4];
            float4 b4 = *(const float4*)&Bs[kk][tx * 4];
            float av[4] = {a4.x, a4.y, a4.z, a4.w};
            float bv[4] = {b4.x, b4.y, b4.z, b4.w};
            #pragma unroll
            for (int i = 0; i < 4; i++)
                #pragma unroll
                for (int j = 0; j < 4; j++)
                    acc[i][j] += av[i] * bv[j];
        }
        __syncthreads();
    }

    #pragma unroll
    for (int i = 0; i < 4; i++) {
        int r = rowBase + ty * 4 + i;
        if (r >= M) continue;
        #pragma unroll
        for (int j = 0; j < 4; j++) {
            int c = colBase + tx * 4 + j;
            if (c >= N) continue;
            float val = alpha * acc[i][j];
            if ((flags & F_DIAG) && r == c) val += diagAdd;
            if (flags & F_BIAS) val += bias[c];
            if (flags & F_RES)  val += resp[(long long)r * N + c];
            if (flags & F_RELU) val = fmaxf(val, 0.f);
            C[(long long)r * N + c] = val;
        }
    }
}

// ---------------- Reductions ----------------
__device__ __forceinline__ float block_reduce_sum(float v, float* sh) {
    int tid = threadIdx.x;
    sh[tid] = v; __syncthreads();
    for (int s = 128; s > 0; s >>= 1) {
        if (tid < s) sh[tid] += sh[tid + s];
        __syncthreads();
    }
    float r = sh[0]; __syncthreads();
    return r;
}
__device__ __forceinline__ float block_reduce_max(float v, float* sh) {
    int tid = threadIdx.x;
    sh[tid] = v; __syncthreads();
    for (int s = 128; s > 0; s >>= 1) {
        if (tid < s) sh[tid] = fmaxf(sh[tid], sh[tid + s]);
        __syncthreads();
    }
    float r = sh[0]; __syncthreads();
    return r;
}

// ---------------- LayerNorm (D=512, block=256, 2 elems/thread) ----------------
__global__ __launch_bounds__(256) void layernorm_kernel(
    const float* __restrict__ x, float* __restrict__ y,
    const float* __restrict__ w, const float* __restrict__ b,
    long long ldx, long long ldy)
{
    __shared__ float sh[256];
    int tid = threadIdx.x;
    const float* xr = x + (long long)blockIdx.x * ldx;
    float* yr = y + (long long)blockIdx.x * ldy;
    float v0 = xr[tid], v1 = xr[tid + 256];
    float mu = block_reduce_sum(v0 + v1, sh) * (1.f / 512.f);
    float d0 = v0 - mu, d1 = v1 - mu;
    float var = block_reduce_sum(d0 * d0 + d1 * d1, sh) * (1.f / 512.f);
    float rstd = 1.f / sqrtf(var + 1e-5f);
    yr[tid]       = d0 * rstd * w[tid]       + b[tid];
    yr[tid + 256] = d1 * rstd * w[tid + 256] + b[tid + 256];
}

// ---------------- Softmax over rows ----------------
__global__ __launch_bounds__(256) void softmax_rows(float* __restrict__ data, int cols)
{
    __shared__ float sh[256];
    float* p = data + (long long)blockIdx.x * cols;
    int tid = threadIdx.x;
    float m = -1e30f;
    for (int j = tid; j < cols; j += 256) m = fmaxf(m, p[j]);
    m = block_reduce_max(m, sh);
    float s = 0.f;
    for (int j = tid; j < cols; j += 256) { float e = expf(p[j] - m); p[j] = e; s += e; }
    s = block_reduce_sum(s, sh);
    float inv = 1.f / s;
    for (int j = tid; j < cols; j += 256) p[j] *= inv;
}

// ---------------- QKV split to head-major ----------------
__global__ void split_qkv_kernel(const float* __restrict__ qkv,
                                 float* __restrict__ q, float* __restrict__ k, float* __restrict__ v)
{
    long long idx = (long long)blockIdx.x * 256 + threadIdx.x;
    if (idx >= (long long)BATCH * NTOK * 3 * DIM) return;
    int c = (int)(idx % (3 * DIM));
    long long bn = idx / (3 * DIM);
    int b = (int)(bn >> 12), n = (int)(bn & 4095);
    int which = c / DIM;
    int hc = c % DIM;
    int h = hc >> 6, d = hc & 63;
    float val = qkv[idx];
    long long dst = (((long long)(b * HEADS + h)) * NTOK + n) * DH + d;
    if (which == 0)      q[dst] = val * 0.125f;   // DIM_HEAD^-0.5
    else if (which == 1) k[dst] = val;
    else                 v[dst] = val;
}

// ---------------- Landmark means ----------------
__global__ void landmark_kernel(const float* __restrict__ src, float* __restrict__ dst)
{
    int idx = blockIdx.x * 256 + threadIdx.x;   // BH*LM*DH = 262144
    if (idx >= BH * LM * DH) return;
    int bh = idx / (LM * DH);
    int j = (idx / DH) % LM;
    int d = idx % DH;
    const float* p = src + ((long long)bh * NTOK + (long long)j * GRP) * DH + d;
    float s = 0.f;
    #pragma unroll
    for (int t = 0; t < GRP; t++) s += p[t * DH];
    dst[idx] = s * (1.f / GRP);
}

// ---------------- pinv helpers ----------------
__global__ void init_scal_kernel(float* s) { if (threadIdx.x < 2) s[threadIdx.x] = 0.f; }

__global__ void abs_sum_max_kernel(const float* __restrict__ x, float* scal, int which)
{
    int idx = blockIdx.x * 256 + threadIdx.x;    // BH*LM = 4096
    if (idx >= BH * LM) return;
    int bh = idx >> 8, i = idx & 255;
    const float* p = x + (long long)bh * LM * LM;
    float s = 0.f;
    if (which == 0) { for (int j = 0; j < LM; j++) s += fabsf(p[i * LM + j]); }   // row sums -> "col"
    else            { for (int j = 0; j < LM; j++) s += fabsf(p[j * LM + i]); }   // col sums -> "row"
    atomicMax((int*)&scal[which], __float_as_int(s));
}

__global__ void zinit_kernel(float* __restrict__ z, const float* __restrict__ x,
                             const float* __restrict__ scal)
{
    long long idx = (long long)blockIdx.x * 256 + threadIdx.x;
    if (idx >= (long long)BH * LM * LM) return;
    int bh = (int)(idx >> 16);
    int i = (int)((idx >> 8) & 255);
    int j = (int)(idx & 255);
    float inv = 1.f / (scal[0] * scal[1]);
    z[idx] = x[(long long)bh * LM * LM + (long long)j * LM + i] * inv;
}

__global__ void negdiag_kernel(float* __restrict__ dst, const float* __restrict__ src, float c)
{
    long long idx = (long long)blockIdx.x * 256 + threadIdx.x;
    if (idx >= (long long)BH * LM * LM) return;
    int i = (int)((idx >> 8) & 255), j = (int)(idx & 255);
    dst[idx] = ((i == j) ? c : 0.f) - src[idx];
}

// ---------------- Depthwise residual conv (kernel 33 over seq dim) ----------------
__global__ void conv_add_kernel(float* __restrict__ ao, const float* __restrict__ v,
                                const float* __restrict__ w)
{
    long long idx = (long long)blockIdx.x * 256 + threadIdx.x;  // BH*NTOK*DH
    if (idx >= (long long)BH * NTOK * DH) return;
    int d = (int)(idx & 63);
    int i = (int)((idx >> 6) & 4095);
    int bh = (int)(idx >> 18);
    int h = bh & 7;
    const float* wp = w + h * 33;
    const float* vp = v + ((long long)bh << 18) + d;
    float s = 0.f;
    #pragma unroll
    for (int t = 0; t < 33; t++) {
        int ii = i + t - 16;
        if (ii >= 0 && ii < NTOK) s += wp[t] * vp[(long long)ii * DH];
    }
    ao[idx] += s;
}

// ---------------- Merge heads [bh,n,64] -> [b,n,512] ----------------
__global__ void merge_heads_kernel(const float* __restrict__ ao, float* __restrict__ out)
{
    long long idx = (long long)blockIdx.x * 256 + threadIdx.x;  // BATCH*NTOK*DIM
    if (idx >= (long long)BATCH * NTOK * DIM) return;
    int c = (int)(idx % DIM);
    long long bn = idx / DIM;
    int b = (int)(bn >> 12), n = (int)(bn & 4095);
    int h = c >> 6, d = c & 63;
    out[idx] = ao[(((long long)(b * HEADS + h)) * NTOK + n) * DH + d];
}

// ---------------- cls token ----------------
__global__ void set_cls_kernel(float* __restrict__ h, const float* __restrict__ cls)
{
    int idx = blockIdx.x * 256 + threadIdx.x;
    if (idx >= BATCH * DIM) return;
    int b = idx >> 9, d = idx & 511;
    h[(long long)b * NTOK * DIM + d] = cls[d];
}

// ---------------- fc2 head ----------------
__global__ void fc2_kernel(const float* __restrict__ clsn, const float* __restrict__ w,
                           const float* __restrict__ b, float* __restrict__ out)
{
    int idx = blockIdx.x * 256 + threadIdx.x;
    if (idx >= BATCH * OUTC) return;
    int bb = idx / OUTC, o = idx % OUTC;
    const float* c = clsn + bb * DIM;
    const float* wp = w + (long long)o * DIM;
    float s = b[o];
    for (int d = 0; d < DIM; d++) s += c[d] * wp[d];
    out[idx] = s;
}

// ---------------- Host side ----------------
static void gemm(const float* A, const float* B, float* C,
                 const float* bias, const float* res,
                 int M, int N, int K, int batch,
                 long long sA, long long sB, long long sC,
                 int flags, float alpha, float diagAdd)
{
    dim3 grid((N + 63) / 64, (M + 63) / 64, batch);
    gemm_kernel<<<grid, 256>>>(A, B, C, bias, res, M, N, K, sA, sB, sC, flags, alpha, diagAdd);
}

static void attention_layer(const float* norm_w, const float* norm_b,
                            const float* qkv_w, const float* out_w, const float* out_b,
                            const float* res_w,
                            float* h, float* xn, float* qkv,
                            float* q, float* k, float* v, float* ql, float* kl,
                            float* s1, float* s2, float* s3,
                            float* za, float* zb, float* xz, float* t1, float* t2,
                            float* av, float* zav, float* ao, float* scal)
{
    const long long SLL = (long long)LM * LM;        // 65536
    layernorm_kernel<<<BATCH * NTOK, 256>>>(h, xn, norm_w, norm_b, DIM, DIM);
    gemm(xn, qkv_w, qkv, nullptr, nullptr, BATCH * NTOK, 3 * DIM, DIM, 1, 0, 0, 0,
         F_TRANSB, 1.f, 0.f);
    split_qkv_kernel<<<(int)(((long long)BATCH * NTOK * 3 * DIM + 255) / 256), 256>>>(qkv, q, k, v);
    landmark_kernel<<<(BH * LM * DH + 255) / 256, 256>>>(q, ql);
    landmark_kernel<<<(BH * LM * DH + 255) / 256, 256>>>(k, kl);

    // attn1 = softmax(q @ kl^T)   [16,4096,256]
    gemm(q, kl, s1, 0, 0, NTOK, LM, DH, BH,
         (long long)NTOK * DH, (long long)LM * DH, (long long)NTOK * LM, F_TRANSB, 1.f, 0.f);
    softmax_rows<<<BH * NTOK, 256>>>(s1, LM);
    // attn2 = softmax(ql @ kl^T)  [16,256,256]
    gemm(ql, kl, s2, 0, 0, LM, LM, DH, BH,
         (long long)LM * DH, (long long)LM * DH, SLL, F_TRANSB, 1.f, 0.f);
    softmax_rows<<<BH * LM, 256>>>(s2, LM);
    // attn3 = softmax(ql @ k^T)   [16,256,4096]
    gemm(ql, k, s3, 0, 0, LM, NTOK, DH, BH,
         (long long)LM * DH, (long long)NTOK * DH, (long long)LM * NTOK, F_TRANSB, 1.f, 0.f);
    softmax_rows<<<BH * LM, 256>>>(s3, NTOK);

    // pinv(attn2) via 6 Newton iterations
    init_scal_kernel<<<1, 32>>>(scal);
    abs_sum_max_kernel<<<(BH * LM + 255) / 256, 256>>>(s2, scal, 0);
    abs_sum_max_kernel<<<(BH * LM + 255) / 256, 256>>>(s2, scal, 1);
    zinit_kernel<<<(int)((BH * SLL) / 256), 256>>>(za, s2, scal);
    float* zc = za; float* zn = zb;
    for (int it = 0; it < 6; it++) {
        gemm(s2, zc, xz, 0, 0, LM, LM, LM, BH, SLL, SLL, SLL, 0, 1.f, 0.f);        // XZ
        negdiag_kernel<<<(int)((BH * SLL) / 256), 256>>>(t1, xz, 7.f);             // 7I - XZ
        gemm(xz, t1, t2, 0, 0, LM, LM, LM, BH, SLL, SLL, SLL, F_DIAG, -1.f, 15.f); // 15I - XZ@T1
        gemm(xz, t2, t1, 0, 0, LM, LM, LM, BH, SLL, SLL, SLL, F_DIAG, -1.f, 13.f); // 13I - XZ@T2
        gemm(zc, t1, zn, 0, 0, LM, LM, LM, BH, SLL, SLL, SLL, 0, 0.25f, 0.f);      // 0.25 Z@T3
        float* t = zc; zc = zn; zn = t;
    }

    // AV = attn3 @ v           [16,256,64]
    gemm(s3, v, av, 0, 0, LM, DH, NTOK, BH,
         (long long)LM * NTOK, (long long)NTOK * DH, (long long)LM * DH, 0, 1.f, 0.f);
    // ZAV = pinv @ AV          [16,256,64]
    gemm(zc, av, zav, 0, 0, LM, DH, LM, BH, SLL, (long long)LM * DH, (long long)LM * DH, 0, 1.f, 0.f);
    // out = attn1 @ ZAV        [16,4096,64]
    gemm(s1, zav, ao, 0, 0, NTOK, DH, LM, BH,
         (long long)NTOK * LM, (long long)LM * DH, (long long)NTOK * DH, 0, 1.f, 0.f);
    // + depthwise conv residual over sequence
    conv_add_kernel<<<(int)(((long long)BH * NTOK * DH + 255) / 256), 256>>>(ao, v, res_w);
    // merge heads -> xn, project + bias + residual add into h
    merge_heads_kernel<<<(int)(((long long)BATCH * NTOK * DIM + 255) / 256), 256>>>(ao, xn);
    gemm(xn, out_w, h, out_b, h, BATCH * NTOK, DIM, DIM, 1, 0, 0, 0,
         F_TRANSB | F_BIAS | F_RES, 1.f, 0.f);
}

extern "C" void kernel_launch(void* const* d_in, const int* in_sizes, int n_in,
                              void* d_out, int out_size)
{
    const float* x        = (const float*)d_in[0];
    const float* fc1_w    = (const float*)d_in[1];
    const float* fc1_b    = (const float*)d_in[2];
    const float* cls_tok  = (const float*)d_in[3];
    const float* l1_nw    = (const float*)d_in[4];
    const float* l1_nb    = (const float*)d_in[5];
    const float* l1_qkv   = (const float*)d_in[6];
    const float* l1_ow    = (const float*)d_in[7];
    const float* l1_ob    = (const float*)d_in[8];
    const float* l1_rw    = (const float*)d_in[9];
    const float* l2_nw    = (const float*)d_in[10];
    const float* l2_nb    = (const float*)d_in[11];
    const float* l2_qkv   = (const float*)d_in[12];
    const float* l2_ow    = (const float*)d_in[13];
    const float* l2_ob    = (const float*)d_in[14];
    const float* l2_rw    = (const float*)d_in[15];
    const float* norm_w   = (const float*)d_in[16];
    const float* norm_b   = (const float*)d_in[17];
    const float* fc2_w    = (const float*)d_in[18];
    const float* fc2_b    = (const float*)d_in[19];
    float* out = (float*)d_out;

    float *h, *xn, *qkv, *q, *k, *v, *ql, *kl, *s1, *s2, *s3;
    float *za, *zb, *xz, *t1, *t2, *av, *zav, *ao, *clsn, *scal;
    cudaGetSymbolAddress((void**)&h, g_h);
    cudaGetSymbolAddress((void**)&xn, g_xn);
    cudaGetSymbolAddress((void**)&qkv, g_qkv);
    cudaGetSymbolAddress((void**)&q, g_q);
    cudaGetSymbolAddress((void**)&k, g_k);
    cudaGetSymbolAddress((void**)&v, g_v);
    cudaGetSymbolAddress((void**)&ql, g_ql);
    cudaGetSymbolAddress((void**)&kl, g_kl);
    cudaGetSymbolAddress((void**)&s1, g_s1);
    cudaGetSymbolAddress((void**)&s2, g_s2);
    cudaGetSymbolAddress((void**)&s3, g_s3);
    cudaGetSymbolAddress((void**)&za, g_za);
    cudaGetSymbolAddress((void**)&zb, g_zb);
    cudaGetSymbolAddress((void**)&xz, g_xz);
    cudaGetSymbolAddress((void**)&t1, g_t1);
    cudaGetSymbolAddress((void**)&t2, g_t2);
    cudaGetSymbolAddress((void**)&av, g_av);
    cudaGetSymbolAddress((void**)&zav, g_zav);
    cudaGetSymbolAddress((void**)&ao, g_ao);
    cudaGetSymbolAddress((void**)&clsn, g_clsn);
    cudaGetSymbolAddress((void**)&scal, g_scal);

    // fc1 + relu into h rows [1..4095] of each batch (row 0 reserved for cls)
    gemm(x, fc1_w, h + DIM, fc1_b, nullptr, NIN, DIM, LIN, BATCH,
         (long long)NIN * LIN, 0, (long long)NTOK * DIM,
         F_TRANSB | F_RELU | F_BIAS, 1.f, 0.f);
    set_cls_kernel<<<(BATCH * DIM + 255) / 256, 256>>>(h, cls_tok);

    attention_layer(l1_nw, l1_nb, l1_qkv, l1_ow, l1_ob, l1_rw,
                    h, xn, qkv, q, k, v, ql, kl, s1, s2, s3,
                    za, zb, xz, t1, t2, av, zav, ao, scal);
    attention_layer(l2_nw, l2_nb, l2_qkv, l2_ow, l2_ob, l2_rw,
                    h, xn, qkv, q, k, v, ql, kl, s1, s2, s3,
                    za, zb, xz, t1, t2, av, zav, ao, scal);

    // final LN on cls rows only (rows 0 and 4096 of h) -> fc2
    layernorm_kernel<<<BATCH, 256>>>(h, clsn, norm_w, norm_b, (long long)NTOK * DIM, DIM);
    fc2_kernel<<<(BATCH * OUTC + 255) / 256, 256>>>(clsn, fc2_w, fc2_b, out);
}

// round 2
// speedup vs baseline: 1.3864x; 1.3864x over previous
#include <cuda_runtime.h>
#include <cuda_bf16.h>

// ---------------- Model constants ----------------
#define BATCH 2
#define NTOK 4096
#define NIN 4095
#define LIN 1024
#define DIM 512
#define HEADS 8
#define DH 64
#define BH (BATCH*HEADS)
#define LM 256
#define GRP 16
#define OUTC 1000

// ---------------- Scratch ----------------
__device__ float g_h   [BATCH*NTOK*DIM];
__device__ float g_xn  [BATCH*NTOK*DIM];
__device__ float g_q   [BH*NTOK*DH];
__device__ float g_k   [BH*NTOK*DH];
__device__ float g_v   [BH*NTOK*DH];
__device__ float g_ql  [BH*LM*DH];
__device__ float g_kl  [BH*LM*DH];
__device__ float g_s1  [BH*NTOK*LM];
__device__ float g_s2  [BH*LM*LM];
__device__ float g_s3  [BH*LM*NTOK];
__device__ float g_za  [BH*LM*LM];
__device__ float g_zb  [BH*LM*LM];
__device__ float g_xz  [BH*LM*LM];
__device__ float g_t1  [BH*LM*LM];
__device__ float g_t2  [BH*LM*LM];
__device__ float g_av  [BH*LM*DH];
__device__ float g_zav [BH*LM*DH];
__device__ float g_ao  [BH*NTOK*DH];
__device__ float g_clsn[BATCH*DIM];
__device__ float g_scal[2];

#define F_TRANSB 1
#define F_RELU   2
#define F_BIAS   4
#define F_RES    8
#define F_QKV    32
#define F_MERGEA 64
#define F_ATOMIC 128

// ================= 128x128x8 double-buffered SGEMM =================
__global__ __launch_bounds__(256) void gemm128_kernel(
    const float* __restrict__ A, const float* __restrict__ B, float* __restrict__ C,
    const float* __restrict__ bias, const float* __restrict__ res,
    float* __restrict__ qk, float* __restrict__ qv,
    int M, int N, int K,
    long long sA, long long sB, long long sC,
    int flags, float alpha, float resAlpha)
{
    __shared__ float As[2][8][128];
    __shared__ float Bs[2][8][128];
    const bool transB = flags & F_TRANSB;
    int bz = blockIdx.z;
    A += bz * sA; B += bz * sB; C += bz * sC;
    const float* resp = (flags & F_RES) ? res + bz * sC : nullptr;

    int tid = threadIdx.x;
    int tx = tid & 15, ty = tid >> 4;
    int rowBase = blockIdx.y * 128;
    int colBase = blockIdx.x * 128;

    int aRow = tid >> 1;
    int aCol = (tid & 1) * 4;
    int bRow, bCol;
    if (!transB) { bRow = tid >> 5; bCol = (tid & 31) * 4; }
    else         { bRow = tid >> 1; bCol = (tid & 1) * 4; }

    float4 aReg, bReg;

    float acc[8][8] = {};

    // --- prologue load tile 0 ---
    {
        int gr = rowBase + aRow;
        if (gr < M) {
            if (flags & F_MERGEA) {
                int b = gr >> 12, n = gr & 4095;
                int kk = aCol;
                int h = kk >> 6, d = kk & 63;
                aReg = *(const float4*)&A[(((long long)(b*HEADS + h) << 12) + n) * DH + d];
            } else {
                aReg = *(const float4*)&A[(long long)gr * K + aCol];
            }
        } else aReg = make_float4(0,0,0,0);
        if (!transB) {
            int gc = colBase + bCol;
            bReg = (gc < N) ? *(const float4*)&B[(long long)bRow * N + gc] : make_float4(0,0,0,0);
        } else {
            int gn = colBase + bRow;
            bReg = (gn < N) ? *(const float4*)&B[(long long)gn * K + bCol] : make_float4(0,0,0,0);
        }
    }
    As[0][aCol+0][aRow] = aReg.x; As[0][aCol+1][aRow] = aReg.y;
    As[0][aCol+2][aRow] = aReg.z; As[0][aCol+3][aRow] = aReg.w;
    if (!transB) *(float4*)&Bs[0][bRow][bCol] = bReg;
    else { Bs[0][bCol+0][bRow]=bReg.x; Bs[0][bCol+1][bRow]=bReg.y;
           Bs[0][bCol+2][bRow]=bReg.z; Bs[0][bCol+3][bRow]=bReg.w; }
    __syncthreads();

    int nt = K >> 3;
    int buf = 0;
    for (int t = 0; t < nt; t++) {
        if (t + 1 < nt) {
            int k0 = (t + 1) << 3;
            int gr = rowBase + aRow;
            if (gr < M) {
                if (flags & F_MERGEA) {
                    int b = gr >> 12, n = gr & 4095;
                    int kk = k0 + aCol;
                    int h = kk >> 6, d = kk & 63;
                    aReg = *(const float4*)&A[(((long long)(b*HEADS + h) << 12) + n) * DH + d];
                } else {
                    aReg = *(const float4*)&A[(long long)gr * K + k0 + aCol];
                }
            } else aReg = make_float4(0,0,0,0);
            if (!transB) {
                int gc = colBase + bCol;
                bReg = (gc < N) ? *(const float4*)&B[(long long)(k0 + bRow) * N + gc] : make_float4(0,0,0,0);
            } else {
                int gn = colBase + bRow;
                bReg = (gn < N) ? *(const float4*)&B[(long long)gn * K + k0 + bCol] : make_float4(0,0,0,0);
            }
        }
        #pragma unroll
        for (int kk = 0; kk < 8; kk++) {
            float4 a0 = *(const float4*)&As[buf][kk][ty*4];
            float4 a1 = *(const float4*)&As[buf][kk][64 + ty*4];
            float4 b0 = *(const float4*)&Bs[buf][kk][tx*4];
            float4 b1 = *(const float4*)&Bs[buf][kk][64 + tx*4];
            float av[8] = {a0.x,a0.y,a0.z,a0.w,a1.x,a1.y,a1.z,a1.w};
            float bv[8] = {b0.x,b0.y,b0.z,b0.w,b1.x,b1.y,b1.z,b1.w};
            #pragma unroll
            for (int i = 0; i < 8; i++)
                #pragma unroll
                for (int j = 0; j < 8; j++)
                    acc[i][j] += av[i] * bv[j];
        }
        if (t + 1 < nt) {
            int nb = buf ^ 1;
            As[nb][aCol+0][aRow] = aReg.x; As[nb][aCol+1][aRow] = aReg.y;
            As[nb][aCol+2][aRow] = aReg.z; As[nb][aCol+3][aRow] = aReg.w;
            if (!transB) *(float4*)&Bs[nb][bRow][bCol] = bReg;
            else { Bs[nb][bCol+0][bRow]=bReg.x; Bs[nb][bCol+1][bRow]=bReg.y;
                   Bs[nb][bCol+2][bRow]=bReg.z; Bs[nb][bCol+3][bRow]=bReg.w; }
            __syncthreads();
        }
        buf ^= 1;
    }

    int rows[8], cols[8];
    #pragma unroll
    for (int i = 0; i < 4; i++) {
        rows[i]   = rowBase + ty*4 + i;
        rows[i+4] = rowBase + 64 + ty*4 + i;
        cols[i]   = colBase + tx*4 + i;
        cols[i+4] = colBase + 64 + tx*4 + i;
    }
    if (flags & F_QKV) {
        #pragma unroll
        for (int i = 0; i < 8; i++) {
            int r = rows[i]; if (r >= M) continue;
            int b = r >> 12, n = r & 4095;
            #pragma unroll
            for (int j = 0; j < 8; j++) {
                int c = cols[j]; if (c >= N) continue;
                float val = alpha * acc[i][j];
                int which = c >> 9;
                int hc = c & 511;
                int h = hc >> 6, d = hc & 63;
                long long dst = (((long long)(b*HEADS + h) << 12) + n) * DH + d;
                if (which == 0)      C[dst]  = val * 0.125f;
                else if (which == 1) qk[dst] = val;
                else                 qv[dst] = val;
            }
        }
    } else {
        #pragma unroll
        for (int i = 0; i < 8; i++) {
            int r = rows[i]; if (r >= M) continue;
            #pragma unroll
            for (int j = 0; j < 8; j++) {
                int c = cols[j]; if (c >= N) continue;
                float val = alpha * acc[i][j];
                if (flags & F_BIAS) val += bias[c];
                if (flags & F_RES)  val += resAlpha * resp[(long long)r * N + c];
                if (flags & F_RELU) val = fmaxf(val, 0.f);
                C[(long long)r * N + c] = val;
            }
        }
    }
}

// ================= 64x64x16 SGEMM (small shapes, split-K) =================
__global__ __launch_bounds__(256) void gemm64_kernel(
    const float* __restrict__ A, const float* __restrict__ B, float* __restrict__ C,
    const float* __restrict__ bias, const float* __restrict__ res,
    int M, int N, int K, int splitK,
    long long sA, long long sB, long long sC,
    int flags, float alpha, float resAlpha)
{
    const bool transB = flags & F_TRANSB;
    int zz = blockIdx.z;
    int bz = zz / splitK;
    int chunk = zz % splitK;
    int kLen = K / splitK;
    int kBeg = chunk * kLen;
    A += bz * sA; B += bz * sB; C += bz * sC;
    const float* resp = (flags & F_RES) ? res + bz * sC : nullptr;

    __shared__ float As[16][68];
    __shared__ float Bs[16][68];

    int tid = threadIdx.x;
    int tx = tid & 15, ty = tid >> 4;
    int rowBase = blockIdx.y * 64;
    int colBase = blockIdx.x * 64;

    float acc[4][4] = {};

    for (int k0 = kBeg; k0 < kBeg + kLen; k0 += 16) {
        #pragma unroll
        for (int i = 0; i < 4; i++) {
            int idx = tid + i * 256;
            int m = idx >> 4, kk = idx & 15;
            int r = rowBase + m;
            As[kk][m] = (r < M) ? A[(long long)r * K + k0 + kk] : 0.f;
        }
        if (!transB) {
            #pragma unroll
            for (int i = 0; i < 4; i++) {
                int idx = tid + i * 256;
                int n = idx & 63, kk = idx >> 6;
                int c = colBase + n;
                Bs[kk][n] = (c < N) ? B[(long long)(k0 + kk) * N + c] : 0.f;
            }
        } else {
            #pragma unroll
            for (int i = 0; i < 4; i++) {
                int idx = tid + i * 256;
                int n = idx >> 4, kk = idx & 15;
                int c = colBase + n;
                Bs[kk][n] = (c < N) ? B[(long long)c * K + k0 + kk] : 0.f;
            }
        }
        __syncthreads();
        #pragma unroll
        for (int kk = 0; kk < 16; kk++) {
            float4 a4 = *(const float4*)&As[kk][ty * 4];
            float4 b4 = *(const float4*)&Bs[kk][tx * 4];
            float av[4] = {a4.x, a4.y, a4.z, a4.w};
            float bv[4] = {b4.x, b4.y, b4.z, b4.w};
            #pragma unroll
            for (int i = 0; i < 4; i++)
                #pragma unroll
                for (int j = 0; j < 4; j++)
                    acc[i][j] += av[i] * bv[j];
        }
        __syncthreads();
    }

    #pragma unroll
    for (int i = 0; i < 4; i++) {
        int r = rowBase + ty * 4 + i;
        if (r >= M) continue;
        #pragma unroll
        for (int j = 0; j < 4; j++) {
            int c = colBase + tx * 4 + j;
            if (c >= N) continue;
            float val = alpha * acc[i][j];
            if (flags & F_ATOMIC) {
                atomicAdd(&C[(long long)r * N + c], val);
            } else {
                if (flags & F_BIAS) val += bias[c];
                if (flags & F_RES)  val += resAlpha * resp[(long long)r * N + c];
                if (flags & F_RELU) val = fmaxf(val, 0.f);
                C[(long long)r * N + c] = val;
            }
        }
    }
}

// ---------------- misc kernels ----------------
__global__ void zero_kernel(float* __restrict__ p, long long n)
{
    long long i = (long long)blockIdx.x * 256 + threadIdx.x;
    if (i < n) p[i] = 0.f;
}

__device__ __forceinline__ float warp_max(float v) {
    #pragma unroll
    for (int o = 16; o; o >>= 1) v = fmaxf(v, __shfl_xor_sync(~0u, v, o));
    return v;
}
__device__ __forceinline__ float warp_sum(float v) {
    #pragma unroll
    for (int o = 16; o; o >>= 1) v += __shfl_xor_sync(~0u, v, o);
    return v;
}

// warp-per-row softmax, 256 cols (registers only)
__global__ __launch_bounds__(256) void softmax256_kernel(float* __restrict__ data, int rows)
{
    int w = (blockIdx.x * 256 + threadIdx.x) >> 5;
    if (w >= rows) return;
    int lane = threadIdx.x & 31;
    float4* p4 = (float4*)(data + (long long)w * 256);
    float4 v0 = p4[lane], v1 = p4[lane + 32];
    float m = fmaxf(fmaxf(fmaxf(v0.x, v0.y), fmaxf(v0.z, v0.w)),
                    fmaxf(fmaxf(v1.x, v1.y), fmaxf(v1.z, v1.w)));
    m = warp_max(m);
    v0.x = __expf(v0.x - m); v0.y = __expf(v0.y - m); v0.z = __expf(v0.z - m); v0.w = __expf(v0.w - m);
    v1.x = __expf(v1.x - m); v1.y = __expf(v1.y - m); v1.z = __expf(v1.z - m); v1.w = __expf(v1.w - m);
    float s = v0.x + v0.y + v0.z + v0.w + v1.x + v1.y + v1.z + v1.w;
    s = warp_sum(s);
    float inv = 1.f / s;
    v0.x *= inv; v0.y *= inv; v0.z *= inv; v0.w *= inv;
    v1.x *= inv; v1.y *= inv; v1.z *= inv; v1.w *= inv;
    p4[lane] = v0; p4[lane + 32] = v1;
}

// block softmax, arbitrary cols (mult of 4), smem-staged single pass
__global__ __launch_bounds__(256) void softmax_big_kernel(float* __restrict__ data, int cols4)
{
    extern __shared__ float buf[];
    __shared__ float red[9];
    float4* p4 = (float4*)(data + (long long)blockIdx.x * (cols4 * 4));
    float4* b4 = (float4*)buf;
    int tid = threadIdx.x;
    float m = -1e30f;
    for (int j = tid; j < cols4; j += 256) {
        float4 v = p4[j]; b4[j] = v;
        m = fmaxf(fmaxf(fmaxf(m, v.x), fmaxf(v.y, v.z)), v.w);
    }
    m = warp_max(m);
    if ((tid & 31) == 0) red[tid >> 5] = m;
    __syncthreads();
    if (tid == 0) {
        float t = red[0];
        #pragma unroll
        for (int i = 1; i < 8; i++) t = fmaxf(t, red[i]);
        red[8] = t;
    }
    __syncthreads();
    m = red[8];
    float s = 0.f;
    for (int j = tid; j < cols4; j += 256) {
        float4 v = b4[j];
        v.x = __expf(v.x - m); v.y = __expf(v.y - m); v.z = __expf(v.z - m); v.w = __expf(v.w - m);
        b4[j] = v;
        s += v.x + v.y + v.z + v.w;
    }
    __syncthreads();
    s = warp_sum(s);
    if ((tid & 31) == 0) red[tid >> 5] = s;
    __syncthreads();
    if (tid == 0) {
        float t = 0.f;
        #pragma unroll
        for (int i = 0; i < 8; i++) t += red[i];
        red[8] = t;
    }
    __syncthreads();
    float inv = 1.f / red[8];
    for (int j = tid; j < cols4; j += 256) {
        float4 v = b4[j];
        v.x *= inv; v.y *= inv; v.z *= inv; v.w *= inv;
        p4[j] = v;
    }
}

// ---------------- LayerNorm ----------------
__device__ __forceinline__ float block_reduce_sum_sh(float v, float* sh) {
    int tid = threadIdx.x;
    v = warp_sum(v);
    if ((tid & 31) == 0) sh[tid >> 5] = v;
    __syncthreads();
    if (tid == 0) {
        float t = 0.f;
        #pragma unroll
        for (int i = 0; i < 8; i++) t += sh[i];
        sh[8] = t;
    }
    __syncthreads();
    float r = sh[8];
    __syncthreads();
    return r;
}

__global__ __launch_bounds__(256) void layernorm_kernel(
    const float* __restrict__ x, float* __restrict__ y,
    const float* __restrict__ w, const float* __restrict__ b,
    long long ldx, long long ldy)
{
    __shared__ float sh[9];
    int tid = threadIdx.x;
    const float* xr = x + (long long)blockIdx.x * ldx;
    float* yr = y + (long long)blockIdx.x * ldy;
    float v0 = xr[tid], v1 = xr[tid + 256];
    float mu = block_reduce_sum_sh(v0 + v1, sh) * (1.f / 512.f);
    float d0 = v0 - mu, d1 = v1 - mu;
    float var = block_reduce_sum_sh(d0 * d0 + d1 * d1, sh) * (1.f / 512.f);
    float rstd = rsqrtf(var + 1e-5f);
    yr[tid]       = d0 * rstd * w[tid]       + b[tid];
    yr[tid + 256] = d1 * rstd * w[tid + 256] + b[tid + 256];
}

// ---------------- Landmark means (float4) ----------------
__global__ void landmark_kernel(const float* __restrict__ src, float* __restrict__ dst)
{
    int idx = blockIdx.x * 256 + threadIdx.x;     // BH*LM*16
    if (idx >= BH * LM * (DH/4)) return;
    int bh = idx >> 12;
    int j = (idx >> 4) & 255;
    int d4 = idx & 15;
    const float4* p = (const float4*)src + ((long long)bh * NTOK + (long long)j * GRP) * 16 + d4;
    float4 s = make_float4(0,0,0,0);
    #pragma unroll
    for (int t = 0; t < GRP; t++) {
        float4 v = p[t * 16];
        s.x += v.x; s.y += v.y; s.z += v.z; s.w += v.w;
    }
    s.x *= (1.f/GRP); s.y *= (1.f/GRP); s.z *= (1.f/GRP); s.w *= (1.f/GRP);
    ((float4*)dst)[idx] = s;
}

// ---------------- pinv scaling ----------------
__global__ void init_scal_kernel(float* s) { if (threadIdx.x < 2) s[threadIdx.x] = 0.f; }

__global__ void abs_row_kernel(const float* __restrict__ x, float* scal)
{
    int w = (blockIdx.x * 256 + threadIdx.x) >> 5;   // row id 0..BH*LM-1
    if (w >= BH * LM) return;
    int lane = threadIdx.x & 31;
    int bh = w >> 8, i = w & 255;
    const float* p = x + ((long long)bh << 16) + (long long)i * 256;
    float s = 0.f;
    for (int j = lane; j < 256; j += 32) s += fabsf(p[j]);
    s = warp_sum(s);
    if (lane == 0) atomicMax((int*)&scal[0], __float_as_int(s));
}

__global__ void abs_col_kernel(const float* __restrict__ x, float* scal)
{
    int idx = blockIdx.x * 256 + threadIdx.x;   // BH*LM
    if (idx >= BH * LM) return;
    int bh = idx >> 8, i = idx & 255;
    const float* p = x + ((long long)bh << 16);
    float s = 0.f;
    for (int j = 0; j < 256; j++) s += fabsf(p[j * 256 + i]);
    atomicMax((int*)&scal[1], __float_as_int(s));
}

__global__ void zinit_kernel(float* __restrict__ z, const float* __restrict__ x,
                             const float* __restrict__ scal)
{
    long long idx = (long long)blockIdx.x * 256 + threadIdx.x;
    if (idx >= (long long)BH * LM * LM) return;
    int bh = (int)(idx >> 16);
    int i = (int)((idx >> 8) & 255);
    int j = (int)(idx & 255);
    float inv = 1.f / (scal[0] * scal[1]);
    z[idx] = x[((long long)bh << 16) + ((long long)j << 8) + i] * inv;
}

// ---------------- Depthwise conv residual ----------------
__global__ void conv_add_kernel(float* __restrict__ ao, const float* __restrict__ v,
                                const float* __restrict__ w)
{
    long long idx = (long long)blockIdx.x * 256 + threadIdx.x;
    if (idx >= (long long)BH * NTOK * DH) return;
    int d = (int)(idx & 63);
    int i = (int)((idx >> 6) & 4095);
    int bh = (int)(idx >> 18);
    int h = bh & 7;
    const float* wp = w + h * 33;
    const float* vp = v + ((long long)bh << 18) + d;
    float s = 0.f;
    #pragma unroll
    for (int t = 0; t < 33; t++) {
        int ii = i + t - 16;
        if (ii >= 0 && ii < NTOK) s += wp[t] * vp[(long long)ii * DH];
    }
    ao[idx] += s;
}

__global__ void set_cls_kernel(float* __restrict__ h, const float* __restrict__ cls)
{
    int idx = blockIdx.x * 256 + threadIdx.x;
    if (idx >= BATCH * DIM) return;
    int b = idx >> 9, d = idx & 511;
    h[(long long)b * NTOK * DIM + d] = cls[d];
}

__global__ void fc2_kernel(const float* __restrict__ clsn, const float* __restrict__ w,
                           const float* __restrict__ b, float* __restrict__ out)
{
    int idx = blockIdx.x * 256 + threadIdx.x;
    if (idx >= BATCH * OUTC) return;
    int bb = idx / OUTC, o = idx % OUTC;
    const float4* c = (const float4*)(clsn + bb * DIM);
    const float4* wp = (const float4*)(w + (long long)o * DIM);
    float s = b[o];
    for (int d = 0; d < DIM/4; d++) {
        float4 cv = c[d], wv = wp[d];
        s += cv.x*wv.x + cv.y*wv.y + cv.z*wv.z + cv.w*wv.w;
    }
    out[idx] = s;
}

// ---------------- Host helpers ----------------
static void g128(const float* A, const float* B, float* C,
                 const float* bias, const float* res, float* qk, float* qv,
                 int M, int N, int K, int batch,
                 long long sA, long long sB, long long sC,
                 int flags, float alpha, float resAlpha)
{
    dim3 grid((N + 127) / 128, (M + 127) / 128, batch);
    gemm128_kernel<<<grid, 256>>>(A, B, C, bias, res, qk, qv,
                                  M, N, K, sA, sB, sC, flags, alpha, resAlpha);
}

static void g64(const float* A, const float* B, float* C,
                const float* bias, const float* res,
                int M, int N, int K, int batch, int splitK,
                long long sA, long long sB, long long sC,
                int flags, float alpha, float resAlpha)
{
    dim3 grid((N + 63) / 64, (M + 63) / 64, batch * splitK);
    gemm64_kernel<<<grid, 256>>>(A, B, C, bias, res, M, N, K, splitK,
                                 sA, sB, sC, flags, alpha, resAlpha);
}

static void attention_layer(const float* norm_w, const float* norm_b,
                            const float* qkv_w, const float* out_w, const float* out_b,
                            const float* res_w,
                            float* h, float* xn,
                            float* q, float* k, float* v, float* ql, float* kl,
                            float* s1, float* s2, float* s3,
                            float* za, float* zb, float* xz, float* t1, float* t2,
                            float* av, float* zav, float* ao, float* scal)
{
    const long long SLL = (long long)LM * LM;
    const long long SQ  = (long long)NTOK * DH;
    const long long SL  = (long long)LM * DH;

    layernorm_kernel<<<BATCH * NTOK, 256>>>(h, xn, norm_w, norm_b, DIM, DIM);

    // qkv GEMM fused with head split + q scaling
    g128(xn, qkv_w, q, nullptr, nullptr, k, v, BATCH * NTOK, 3 * DIM, DIM, 1, 0, 0, 0,
         F_TRANSB | F_QKV, 1.f, 0.f);

    landmark_kernel<<<(BH * LM * (DH/4) + 255) / 256, 256>>>(q, ql);
    landmark_kernel<<<(BH * LM * (DH/4) + 255) / 256, 256>>>(k, kl);

    // attn1 = softmax(q @ kl^T)   [16,4096,256]
    g128(q, kl, s1, 0, 0, 0, 0, NTOK, LM, DH, BH, SQ, SL, (long long)NTOK * LM, F_TRANSB, 1.f, 0.f);
    softmax256_kernel<<<(BH * NTOK * 32 + 255) / 256, 256>>>(s1, BH * NTOK);
    // attn2 = softmax(ql @ kl^T)  [16,256,256]
    g64(ql, kl, s2, 0, 0, LM, LM, DH, BH, 1, SL, SL, SLL, F_TRANSB, 1.f, 0.f);
    softmax256_kernel<<<(BH * LM * 32 + 255) / 256, 256>>>(s2, BH * LM);
    // attn3 = softmax(ql @ k^T)   [16,256,4096]
    g128(ql, k, s3, 0, 0, 0, 0, LM, NTOK, DH, BH, SL, SQ, (long long)LM * NTOK, F_TRANSB, 1.f, 0.f);
    softmax_big_kernel<<<BH * LM, 256, NTOK * 4>>>(s3, NTOK / 4);

    // pinv(attn2): z0 = s2^T / (max_row * max_col)
    init_scal_kernel<<<1, 32>>>(scal);
    abs_row_kernel<<<(BH * LM * 32 + 255) / 256, 256>>>(s2, scal);
    abs_col_kernel<<<(BH * LM + 255) / 256, 256>>>(s2, scal);
    zinit_kernel<<<(int)((BH * SLL) / 256), 256>>>(za, s2, scal);

    float* zc = za; float* zn = zb;
    for (int it = 0; it < 6; it++) {
        // xz = s2 @ z
        g64(s2, zc, xz, 0, 0, LM, LM, LM, BH, 1, SLL, SLL, SLL, 0, 1.f, 0.f);
        // u = 7*xz - xz@xz
        g64(xz, xz, t1, 0, xz, LM, LM, LM, BH, 1, SLL, SLL, SLL, F_RES, -1.f, 7.f);
        // v = 15*xz - xz@u
        g64(xz, t1, t2, 0, xz, LM, LM, LM, BH, 1, SLL, SLL, SLL, F_RES, -1.f, 15.f);
        // zn = 3.25*z - 0.25*z@v
        g64(zc, t2, zn, 0, zc, LM, LM, LM, BH, 1, SLL, SLL, SLL, F_RES, -0.25f, 3.25f);
        float* t = zc; zc = zn; zn = t;
    }

    // AV = attn3 @ v   (split-K=8, atomic)
    zero_kernel<<<(BH * LM * DH + 255) / 256, 256>>>(av, (long long)BH * LM * DH);
    g64(s3, v, av, 0, 0, LM, DH, NTOK, BH, 8,
        (long long)LM * NTOK, SQ, SL, F_ATOMIC, 1.f, 0.f);
    // ZAV = pinv @ AV  (split-K=2, atomic)
    zero_kernel<<<(BH * LM * DH + 255) / 256, 256>>>(zav, (long long)BH * LM * DH);
    g64(zc, av, zav, 0, 0, LM, DH, LM, BH, 2, SLL, SL, SL, F_ATOMIC, 1.f, 0.f);
    // out = attn1 @ ZAV
    g64(s1, zav, ao, 0, 0, NTOK, DH, LM, BH, 1,
        (long long)NTOK * LM, SL, SQ, 0, 1.f, 0.f);
    // depthwise conv residual
    conv_add_kernel<<<(int)(((long long)BH * NTOK * DH + 255) / 256), 256>>>(ao, v, res_w);
    // out-proj reading head-major ao directly (merge fused into A-loader), +bias +residual into h
    g128(ao, out_w, h, out_b, h, 0, 0, BATCH * NTOK, DIM, DIM, 1, 0, 0, 0,
         F_TRANSB | F_BIAS | F_RES | F_MERGEA, 1.f, 1.f);
}

extern "C" void kernel_launch(void* const* d_in, const int* in_sizes, int n_in,
                              void* d_out, int out_size)
{
    const float* x        = (const float*)d_in[0];
    const float* fc1_w    = (const float*)d_in[1];
    const float* fc1_b    = (const float*)d_in[2];
    const float* cls_tok  = (const float*)d_in[3];
    const float* l1_nw    = (const float*)d_in[4];
    const float* l1_nb    = (const float*)d_in[5];
    const float* l1_qkv   = (const float*)d_in[6];
    const float* l1_ow    = (const float*)d_in[7];
    const float* l1_ob    = (const float*)d_in[8];
    const float* l1_rw    = (const float*)d_in[9];
    const float* l2_nw    = (const float*)d_in[10];
    const float* l2_nb    = (const float*)d_in[11];
    const float* l2_qkv   = (const float*)d_in[12];
    const float* l2_ow    = (const float*)d_in[13];
    const float* l2_ob    = (const float*)d_in[14];
    const float* l2_rw    = (const float*)d_in[15];
    const float* norm_w   = (const float*)d_in[16];
    const float* norm_b   = (const float*)d_in[17];
    const float* fc2_w    = (const float*)d_in[18];
    const float* fc2_b    = (const float*)d_in[19];
    float* out = (float*)d_out;

    float *h, *xn, *q, *k, *v, *ql, *kl, *s1, *s2, *s3;
    float *za, *zb, *xz, *t1, *t2, *av, *zav, *ao, *clsn, *scal;
    cudaGetSymbolAddress((void**)&h, g_h);
    cudaGetSymbolAddress((void**)&xn, g_xn);
    cudaGetSymbolAddress((void**)&q, g_q);
    cudaGetSymbolAddress((void**)&k, g_k);
    cudaGetSymbolAddress((void**)&v, g_v);
    cudaGetSymbolAddress((void**)&ql, g_ql);
    cudaGetSymbolAddress((void**)&kl, g_kl);
    cudaGetSymbolAddress((void**)&s1, g_s1);
    cudaGetSymbolAddress((void**)&s2, g_s2);
    cudaGetSymbolAddress((void**)&s3, g_s3);
    cudaGetSymbolAddress((void**)&za, g_za);
    cudaGetSymbolAddress((void**)&zb, g_zb);
    cudaGetSymbolAddress((void**)&xz, g_xz);
    cudaGetSymbolAddress((void**)&t1, g_t1);
    cudaGetSymbolAddress((void**)&t2, g_t2);
    cudaGetSymbolAddress((void**)&av, g_av);
    cudaGetSymbolAddress((void**)&zav, g_zav);
    cudaGetSymbolAddress((void**)&ao, g_ao);
    cudaGetSymbolAddress((void**)&clsn, g_clsn);
    cudaGetSymbolAddress((void**)&scal, g_scal);

    // fc1 + relu into rows [1..4095] of each batch
    g128(x, fc1_w, h + DIM, fc1_b, nullptr, nullptr, nullptr, NIN, DIM, LIN, BATCH,
         (long long)NIN * LIN, 0, (long long)NTOK * DIM,
         F_TRANSB | F_RELU | F_BIAS, 1.f, 0.f);
    set_cls_kernel<<<(BATCH * DIM + 255) / 256, 256>>>(h, cls_tok);

    attention_layer(l1_nw, l1_nb, l1_qkv, l1_ow, l1_ob, l1_rw,
                    h, xn, q, k, v, ql, kl, s1, s2, s3,
                    za, zb, xz, t1, t2, av, zav, ao, scal);
    attention_layer(l2_nw, l2_nb, l2_qkv, l2_ow, l2_ob, l2_rw,
                    h, xn, q, k, v, ql, kl, s1, s2, s3,
                    za, zb, xz, t1, t2, av, zav, ao, scal);

    layernorm_kernel<<<BATCH, 256>>>(h, clsn, norm_w, norm_b, (long long)NTOK * DIM, DIM);
    fc2_kernel<<<(BATCH * OUTC + 255) / 256, 256>>>(clsn, fc2_w, fc2_b, out);
}

// round 3
// speedup vs baseline: 1.3924x; 1.0044x over previous
#include <cuda_runtime.h>
#include <cuda_bf16.h>

// ---------------- Model constants ----------------
#define BATCH 2
#define NTOK 4096
#define NIN 4095
#define LIN 1024
#define DIM 512
#define HEADS 8
#define DH 64
#define BH (BATCH*HEADS)
#define LM 256
#define GRP 16
#define OUTC 1000

// ---------------- Scratch ----------------
__device__ float g_h   [BATCH*NTOK*DIM];
__device__ float g_xn  [BATCH*NTOK*DIM];
__device__ float g_q   [BH*NTOK*DH];
__device__ float g_k   [BH*NTOK*DH];
__device__ float g_v   [BH*NTOK*DH];
__device__ float g_ql  [BH*LM*DH];
__device__ float g_kl  [BH*LM*DH];
__device__ float g_s1  [BH*NTOK*LM];
__device__ float g_s2  [BH*LM*LM];
__device__ float g_s3  [BH*LM*NTOK];
__device__ float g_za  [BH*LM*LM];
__device__ float g_zb  [BH*LM*LM];
__device__ float g_xz  [BH*LM*LM];
__device__ float g_t1  [BH*LM*LM];
__device__ float g_t2  [BH*LM*LM];
__device__ float g_av  [BH*LM*DH];
__device__ float g_zav [BH*LM*DH];
__device__ float g_ao  [BH*NTOK*DH];
__device__ float g_clsn[BATCH*DIM];
__device__ float g_scal[2];

#define F_TRANSB 1
#define F_RELU   2
#define F_BIAS   4
#define F_RES    8
#define F_QKV    32
#define F_MERGEA 64
#define F_ATOMIC 128

// ================= 128x128x8 double-buffered SGEMM =================
__global__ __launch_bounds__(256) void gemm128_kernel(
    const float* __restrict__ A, const float* __restrict__ B, float* __restrict__ C,
    const float* __restrict__ bias, const float* __restrict__ res,
    float* __restrict__ qk, float* __restrict__ qv,
    int M, int N, int K,
    long long sA, long long sB, long long sC,
    int flags, float alpha, float resAlpha)
{
    __shared__ float As[2][8][128];
    __shared__ float Bs[2][8][128];
    const bool transB = flags & F_TRANSB;
    int bz = blockIdx.z;
    A += bz * sA; B += bz * sB; C += bz * sC;
    const float* resp = (flags & F_RES) ? res + bz * sC : nullptr;

    int tid = threadIdx.x;
    int tx = tid & 15, ty = tid >> 4;
    int rowBase = blockIdx.y * 128;
    int colBase = blockIdx.x * 128;

    int aRow = tid >> 1;
    int aCol = (tid & 1) * 4;
    int bRow, bCol;
    if (!transB) { bRow = tid >> 5; bCol = (tid & 31) * 4; }
    else         { bRow = tid >> 1; bCol = (tid & 1) * 4; }

    float4 aReg, bReg;

    float acc[8][8] = {};

    // --- prologue load tile 0 ---
    {
        int gr = rowBase + aRow;
        if (gr < M) {
            if (flags & F_MERGEA) {
                int b = gr >> 12, n = gr & 4095;
                int kk = aCol;
                int h = kk >> 6, d = kk & 63;
                aReg = *(const float4*)&A[(((long long)(b*HEADS + h) << 12) + n) * DH + d];
            } else {
                aReg = *(const float4*)&A[(long long)gr * K + aCol];
            }
        } else aReg = make_float4(0,0,0,0);
        if (!transB) {
            int gc = colBase + bCol;
            bReg = (gc < N) ? *(const float4*)&B[(long long)bRow * N + gc] : make_float4(0,0,0,0);
        } else {
            int gn = colBase + bRow;
            bReg = (gn < N) ? *(const float4*)&B[(long long)gn * K + bCol] : make_float4(0,0,0,0);
        }
    }
    As[0][aCol+0][aRow] = aReg.x; As[0][aCol+1][aRow] = aReg.y;
    As[0][aCol+2][aRow] = aReg.z; As[0][aCol+3][aRow] = aReg.w;
    if (!transB) *(float4*)&Bs[0][bRow][bCol] = bReg;
    else { Bs[0][bCol+0][bRow]=bReg.x; Bs[0][bCol+1][bRow]=bReg.y;
           Bs[0][bCol+2][bRow]=bReg.z; Bs[0][bCol+3][bRow]=bReg.w; }
    __syncthreads();

    int nt = K >> 3;
    int buf = 0;
    for (int t = 0; t < nt; t++) {
        if (t + 1 < nt) {
            int k0 = (t + 1) << 3;
            int gr = rowBase + aRow;
            if (gr < M) {
                if (flags & F_MERGEA) {
                    int b = gr >> 12, n = gr & 4095;
                    int kk = k0 + aCol;
                    int h = kk >> 6, d = kk & 63;
                    aReg = *(const float4*)&A[(((long long)(b*HEADS + h) << 12) + n) * DH + d];
                } else {
                    aReg = *(const float4*)&A[(long long)gr * K + k0 + aCol];
                }
            } else aReg = make_float4(0,0,0,0);
            if (!transB) {
                int gc = colBase + bCol;
                bReg = (gc < N) ? *(const float4*)&B[(long long)(k0 + bRow) * N + gc] : make_float4(0,0,0,0);
            } else {
                int gn = colBase + bRow;
                bReg = (gn < N) ? *(const float4*)&B[(long long)gn * K + k0 + bCol] : make_float4(0,0,0,0);
            }
        }
        #pragma unroll
        for (int kk = 0; kk < 8; kk++) {
            float4 a0 = *(const float4*)&As[buf][kk][ty*4];
            float4 a1 = *(const float4*)&As[buf][kk][64 + ty*4];
            float4 b0 = *(const float4*)&Bs[buf][kk][tx*4];
            float4 b1 = *(const float4*)&Bs[buf][kk][64 + tx*4];
            float av[8] = {a0.x,a0.y,a0.z,a0.w,a1.x,a1.y,a1.z,a1.w};
            float bv[8] = {b0.x,b0.y,b0.z,b0.w,b1.x,b1.y,b1.z,b1.w};
            #pragma unroll
            for (int i = 0; i < 8; i++)
                #pragma unroll
                for (int j = 0; j < 8; j++)
                    acc[i][j] += av[i] * bv[j];
        }
        if (t + 1 < nt) {
            int nb = buf ^ 1;
            As[nb][aCol+0][aRow] = aReg.x; As[nb][aCol+1][aRow] = aReg.y;
            As[nb][aCol+2][aRow] = aReg.z; As[nb][aCol+3][aRow] = aReg.w;
            if (!transB) *(float4*)&Bs[nb][bRow][bCol] = bReg;
            else { Bs[nb][bCol+0][bRow]=bReg.x; Bs[nb][bCol+1][bRow]=bReg.y;
                   Bs[nb][bCol+2][bRow]=bReg.z; Bs[nb][bCol+3][bRow]=bReg.w; }
            __syncthreads();
        }
        buf ^= 1;
    }

    int rows[8], cols[8];
    #pragma unroll
    for (int i = 0; i < 4; i++) {
        rows[i]   = rowBase + ty*4 + i;
        rows[i+4] = rowBase + 64 + ty*4 + i;
        cols[i]   = colBase + tx*4 + i;
        cols[i+4] = colBase + 64 + tx*4 + i;
    }
    if (flags & F_QKV) {
        #pragma unroll
        for (int i = 0; i < 8; i++) {
            int r = rows[i]; if (r >= M) continue;
            int b = r >> 12, n = r & 4095;
            #pragma unroll
            for (int j = 0; j < 8; j++) {
                int c = cols[j]; if (c >= N) continue;
                float val = alpha * acc[i][j];
                int which = c >> 9;
                int hc = c & 511;
                int h = hc >> 6, d = hc & 63;
                long long dst = (((long long)(b*HEADS + h) << 12) + n) * DH + d;
                if (which == 0)      C[dst]  = val * 0.125f;
                else if (which == 1) qk[dst] = val;
                else                 qv[dst] = val;
            }
        }
    } else {
        #pragma unroll
        for (int i = 0; i < 8; i++) {
            int r = rows[i]; if (r >= M) continue;
            #pragma unroll
            for (int j = 0; j < 8; j++) {
                int c = cols[j]; if (c >= N) continue;
                float val = alpha * acc[i][j];
                if (flags & F_BIAS) val += bias[c];
                if (flags & F_RES)  val += resAlpha * resp[(long long)r * N + c];
                if (flags & F_RELU) val = fmaxf(val, 0.f);
                C[(long long)r * N + c] = val;
            }
        }
    }
}

// ================= 64x64x16 SGEMM (small shapes, split-K) =================
__global__ __launch_bounds__(256) void gemm64_kernel(
    const float* __restrict__ A, const float* __restrict__ B, float* __restrict__ C,
    const float* __restrict__ bias, const float* __restrict__ res,
    int M, int N, int K, int splitK,
    long long sA, long long sB, long long sC,
    int flags, float alpha, float resAlpha)
{
    const bool transB = flags & F_TRANSB;
    int zz = blockIdx.z;
    int bz = zz / splitK;
    int chunk = zz % splitK;
    int kLen = K / splitK;
    int kBeg = chunk * kLen;
    A += bz * sA; B += bz * sB; C += bz * sC;
    const float* resp = (flags & F_RES) ? res + bz * sC : nullptr;

    __shared__ float As[16][68];
    __shared__ float Bs[16][68];

    int tid = threadIdx.x;
    int tx = tid & 15, ty = tid >> 4;
    int rowBase = blockIdx.y * 64;
    int colBase = blockIdx.x * 64;

    float acc[4][4] = {};

    for (int k0 = kBeg; k0 < kBeg + kLen; k0 += 16) {
        #pragma unroll
        for (int i = 0; i < 4; i++) {
            int idx = tid + i * 256;
            int m = idx >> 4, kk = idx & 15;
            int r = rowBase + m;
            As[kk][m] = (r < M) ? A[(long long)r * K + k0 + kk] : 0.f;
        }
        if (!transB) {
            #pragma unroll
            for (int i = 0; i < 4; i++) {
                int idx = tid + i * 256;
                int n = idx & 63, kk = idx >> 6;
                int c = colBase + n;
                Bs[kk][n] = (c < N) ? B[(long long)(k0 + kk) * N + c] : 0.f;
            }
        } else {
            #pragma unroll
            for (int i = 0; i < 4; i++) {
                int idx = tid + i * 256;
                int n = idx >> 4, kk = idx & 15;
                int c = colBase + n;
                Bs[kk][n] = (c < N) ? B[(long long)c * K + k0 + kk] : 0.f;
            }
        }
        __syncthreads();
        #pragma unroll
        for (int kk = 0; kk < 16; kk++) {
            float4 a4 = *(const float4*)&As[kk][ty * 4];
            float4 b4 = *(const float4*)&Bs[kk][tx * 4];
            float av[4] = {a4.x, a4.y, a4.z, a4.w};
            float bv[4] = {b4.x, b4.y, b4.z, b4.w};
            #pragma unroll
            for (int i = 0; i < 4; i++)
                #pragma unroll
                for (int j = 0; j < 4; j++)
                    acc[i][j] += av[i] * bv[j];
        }
        __syncthreads();
    }

    #pragma unroll
    for (int i = 0; i < 4; i++) {
        int r = rowBase + ty * 4 + i;
        if (r >= M) continue;
        #pragma unroll
        for (int j = 0; j < 4; j++) {
            int c = colBase + tx * 4 + j;
            if (c >= N) continue;
            float val = alpha * acc[i][j];
            if (flags & F_ATOMIC) {
                atomicAdd(&C[(long long)r * N + c], val);
            } else {
                if (flags & F_BIAS) val += bias[c];
                if (flags & F_RES)  val += resAlpha * resp[(long long)r * N + c];
                if (flags & F_RELU) val = fmaxf(val, 0.f);
                C[(long long)r * N + c] = val;
            }
        }
    }
}

// ---------------- misc kernels ----------------
__global__ void zero_kernel(float* __restrict__ p, long long n)
{
    long long i = (long long)blockIdx.x * 256 + threadIdx.x;
    if (i < n) p[i] = 0.f;
}

__device__ __forceinline__ float warp_max(float v) {
    #pragma unroll
    for (int o = 16; o; o >>= 1) v = fmaxf(v, __shfl_xor_sync(~0u, v, o));
    return v;
}
__device__ __forceinline__ float warp_sum(float v) {
    #pragma unroll
    for (int o = 16; o; o >>= 1) v += __shfl_xor_sync(~0u, v, o);
    return v;
}

// warp-per-row softmax, 256 cols (registers only)
__global__ __launch_bounds__(256) void softmax256_kernel(float* __restrict__ data, int rows)
{
    int w = (blockIdx.x * 256 + threadIdx.x) >> 5;
    if (w >= rows) return;
    int lane = threadIdx.x & 31;
    float4* p4 = (float4*)(data + (long long)w * 256);
    float4 v0 = p4[lane], v1 = p4[lane + 32];
    float m = fmaxf(fmaxf(fmaxf(v0.x, v0.y), fmaxf(v0.z, v0.w)),
                    fmaxf(fmaxf(v1.x, v1.y), fmaxf(v1.z, v1.w)));
    m = warp_max(m);
    v0.x = __expf(v0.x - m); v0.y = __expf(v0.y - m); v0.z = __expf(v0.z - m); v0.w = __expf(v0.w - m);
    v1.x = __expf(v1.x - m); v1.y = __expf(v1.y - m); v1.z = __expf(v1.z - m); v1.w = __expf(v1.w - m);
    float s = v0.x + v0.y + v0.z + v0.w + v1.x + v1.y + v1.z + v1.w;
    s = warp_sum(s);
    float inv = 1.f / s;
    v0.x *= inv; v0.y *= inv; v0.z *= inv; v0.w *= inv;
    v1.x *= inv; v1.y *= inv; v1.z *= inv; v1.w *= inv;
    p4[lane] = v0; p4[lane + 32] = v1;
}

// block softmax, arbitrary cols (mult of 4), smem-staged single pass
__global__ __launch_bounds__(256) void softmax_big_kernel(float* __restrict__ data, int cols4)
{
    extern __shared__ float buf[];
    __shared__ float red[9];
    float4* p4 = (float4*)(data + (long long)blockIdx.x * (cols4 * 4));
    float4* b4 = (float4*)buf;
    int tid = threadIdx.x;
    float m = -1e30f;
    for (int j = tid; j < cols4; j += 256) {
        float4 v = p4[j]; b4[j] = v;
        m = fmaxf(fmaxf(fmaxf(m, v.x), fmaxf(v.y, v.z)), v.w);
    }
    m = warp_max(m);
    if ((tid & 31) == 0) red[tid >> 5] = m;
    __syncthreads();
    if (tid == 0) {
        float t = red[0];
        #pragma unroll
        for (int i = 1; i < 8; i++) t = fmaxf(t, red[i]);
        red[8] = t;
    }
    __syncthreads();
    m = red[8];
    float s = 0.f;
    for (int j = tid; j < cols4; j += 256) {
        float4 v = b4[j];
        v.x = __expf(v.x - m); v.y = __expf(v.y - m); v.z = __expf(v.z - m); v.w = __expf(v.w - m);
        b4[j] = v;
        s += v.x + v.y + v.z + v.w;
    }
    __syncthreads();
    s = warp_sum(s);
    if ((tid & 31) == 0) red[tid >> 5] = s;
    __syncthreads();
    if (tid == 0) {
        float t = 0.f;
        #pragma unroll
        for (int i = 0; i < 8; i++) t += red[i];
        red[8] = t;
    }
    __syncthreads();
    float inv = 1.f / red[8];
    for (int j = tid; j < cols4; j += 256) {
        float4 v = b4[j];
        v.x *= inv; v.y *= inv; v.z *= inv; v.w *= inv;
        p4[j] = v;
    }
}

// ---------------- LayerNorm ----------------
__device__ __forceinline__ float block_reduce_sum_sh(float v, float* sh) {
    int tid = threadIdx.x;
    v = warp_sum(v);
    if ((tid & 31) == 0) sh[tid >> 5] = v;
    __syncthreads();
    if (tid == 0) {
        float t = 0.f;
        #pragma unroll
        for (int i = 0; i < 8; i++) t += sh[i];
        sh[8] = t;
    }
    __syncthreads();
    float r = sh[8];
    __syncthreads();
    return r;
}

__global__ __launch_bounds__(256) void layernorm_kernel(
    const float* __restrict__ x, float* __restrict__ y,
    const float* __restrict__ w, const float* __restrict__ b,
    long long ldx, long long ldy)
{
    __shared__ float sh[9];
    int tid = threadIdx.x;
    const float* xr = x + (long long)blockIdx.x * ldx;
    float* yr = y + (long long)blockIdx.x * ldy;
    float v0 = xr[tid], v1 = xr[tid + 256];
    float mu = block_reduce_sum_sh(v0 + v1, sh) * (1.f / 512.f);
    float d0 = v0 - mu, d1 = v1 - mu;
    float var = block_reduce_sum_sh(d0 * d0 + d1 * d1, sh) * (1.f / 512.f);
    float rstd = rsqrtf(var + 1e-5f);
    yr[tid]       = d0 * rstd * w[tid]       + b[tid];
    yr[tid + 256] = d1 * rstd * w[tid + 256] + b[tid + 256];
}

// ---------------- Landmark means (float4) ----------------
__global__ void landmark_kernel(const float* __restrict__ src, float* __restrict__ dst)
{
    int idx = blockIdx.x * 256 + threadIdx.x;     // BH*LM*16
    if (idx >= BH * LM * (DH/4)) return;
    int bh = idx >> 12;
    int j = (idx >> 4) & 255;
    int d4 = idx & 15;
    const float4* p = (const float4*)src + ((long long)bh * NTOK + (long long)j * GRP) * 16 + d4;
    float4 s = make_float4(0,0,0,0);
    #pragma unroll
    for (int t = 0; t < GRP; t++) {
        float4 v = p[t * 16];
        s.x += v.x; s.y += v.y; s.z += v.z; s.w += v.w;
    }
    s.x *= (1.f/GRP); s.y *= (1.f/GRP); s.z *= (1.f/GRP); s.w *= (1.f/GRP);
    ((float4*)dst)[idx] = s;
}

// ---------------- pinv scaling ----------------
__global__ void init_scal_kernel(float* s) { if (threadIdx.x < 2) s[threadIdx.x] = 0.f; }

__global__ void abs_row_kernel(const float* __restrict__ x, float* scal)
{
    int w = (blockIdx.x * 256 + threadIdx.x) >> 5;   // row id 0..BH*LM-1
    if (w >= BH * LM) return;
    int lane = threadIdx.x & 31;
    int bh = w >> 8, i = w & 255;
    const float* p = x + ((long long)bh << 16) + (long long)i * 256;
    float s = 0.f;
    for (int j = lane; j < 256; j += 32) s += fabsf(p[j]);
    s = warp_sum(s);
    if (lane == 0) atomicMax((int*)&scal[0], __float_as_int(s));
}

__global__ void abs_col_kernel(const float* __restrict__ x, float* scal)
{
    int idx = blockIdx.x * 256 + threadIdx.x;   // BH*LM
    if (idx >= BH * LM) return;
    int bh = idx >> 8, i = idx & 255;
    const float* p = x + ((long long)bh << 16);
    float s = 0.f;
    for (int j = 0; j < 256; j++) s += fabsf(p[j * 256 + i]);
    atomicMax((int*)&scal[1], __float_as_int(s));
}

__global__ void zinit_kernel(float* __restrict__ z, const float* __restrict__ x,
                             const float* __restrict__ scal)
{
    long long idx = (long long)blockIdx.x * 256 + threadIdx.x;
    if (idx >= (long long)BH * LM * LM) return;
    int bh = (int)(idx >> 16);
    int i = (int)((idx >> 8) & 255);
    int j = (int)(idx & 255);
    float inv = 1.f / (scal[0] * scal[1]);
    z[idx] = x[((long long)bh << 16) + ((long long)j << 8) + i] * inv;
}

// ---------------- Depthwise conv residual ----------------
__global__ void conv_add_kernel(float* __restrict__ ao, const float* __restrict__ v,
                                const float* __restrict__ w)
{
    long long idx = (long long)blockIdx.x * 256 + threadIdx.x;
    if (idx >= (long long)BH * NTOK * DH) return;
    int d = (int)(idx & 63);
    int i = (int)((idx >> 6) & 4095);
    int bh = (int)(idx >> 18);
    int h = bh & 7;
    const float* wp = w + h * 33;
    const float* vp = v + ((long long)bh << 18) + d;
    float s = 0.f;
    #pragma unroll
    for (int t = 0; t < 33; t++) {
        int ii = i + t - 16;
        if (ii >= 0 && ii < NTOK) s += wp[t] * vp[(long long)ii * DH];
    }
    ao[idx] += s;
}

__global__ void set_cls_kernel(float* __restrict__ h, const float* __restrict__ cls)
{
    int idx = blockIdx.x * 256 + threadIdx.x;
    if (idx >= BATCH * DIM) return;
    int b = idx >> 9, d = idx & 511;
    h[(long long)b * NTOK * DIM + d] = cls[d];
}

__global__ void fc2_kernel(const float* __restrict__ clsn, const float* __restrict__ w,
                           const float* __restrict__ b, float* __restrict__ out)
{
    int idx = blockIdx.x * 256 + threadIdx.x;
    if (idx >= BATCH * OUTC) return;
    int bb = idx / OUTC, o = idx % OUTC;
    const float4* c = (const float4*)(clsn + bb * DIM);
    const float4* wp = (const float4*)(w + (long long)o * DIM);
    float s = b[o];
    for (int d = 0; d < DIM/4; d++) {
        float4 cv = c[d], wv = wp[d];
        s += cv.x*wv.x + cv.y*wv.y + cv.z*wv.z + cv.w*wv.w;
    }
    out[idx] = s;
}

// ---------------- Host helpers ----------------
static void g128(const float* A, const float* B, float* C,
                 const float* bias, const float* res, float* qk, float* qv,
                 int M, int N, int K, int batch,
                 long long sA, long long sB, long long sC,
                 int flags, float alpha, float resAlpha)
{
    dim3 grid((N + 127) / 128, (M + 127) / 128, batch);
    gemm128_kernel<<<grid, 256>>>(A, B, C, bias, res, qk, qv,
                                  M, N, K, sA, sB, sC, flags, alpha, resAlpha);
}

static void g64(const float* A, const float* B, float* C,
                const float* bias, const float* res,
                int M, int N, int K, int batch, int splitK,
                long long sA, long long sB, long long sC,
                int flags, float alpha, float resAlpha)
{
    dim3 grid((N + 63) / 64, (M + 63) / 64, batch * splitK);
    gemm64_kernel<<<grid, 256>>>(A, B, C, bias, res, M, N, K, splitK,
                                 sA, sB, sC, flags, alpha, resAlpha);
}

static void attention_layer(const float* norm_w, const float* norm_b,
                            const float* qkv_w, const float* out_w, const float* out_b,
                            const float* res_w,
                            float* h, float* xn,
                            float* q, float* k, float* v, float* ql, float* kl,
                            float* s1, float* s2, float* s3,
                            float* za, float* zb, float* xz, float* t1, float* t2,
                            float* av, float* zav, float* ao, float* scal)
{
    const long long SLL = (long long)LM * LM;
    const long long SQ  = (long long)NTOK * DH;
    const long long SL  = (long long)LM * DH;

    layernorm_kernel<<<BATCH * NTOK, 256>>>(h, xn, norm_w, norm_b, DIM, DIM);

    // qkv GEMM fused with head split + q scaling
    g128(xn, qkv_w, q, nullptr, nullptr, k, v, BATCH * NTOK, 3 * DIM, DIM, 1, 0, 0, 0,
         F_TRANSB | F_QKV, 1.f, 0.f);

    landmark_kernel<<<(BH * LM * (DH/4) + 255) / 256, 256>>>(q, ql);
    landmark_kernel<<<(BH * LM * (DH/4) + 255) / 256, 256>>>(k, kl);

    // attn1 = softmax(q @ kl^T)   [16,4096,256]
    g128(q, kl, s1, 0, 0, 0, 0, NTOK, LM, DH, BH, SQ, SL, (long long)NTOK * LM, F_TRANSB, 1.f, 0.f);
    softmax256_kernel<<<(BH * NTOK * 32 + 255) / 256, 256>>>(s1, BH * NTOK);
    // attn2 = softmax(ql @ kl^T)  [16,256,256]
    g64(ql, kl, s2, 0, 0, LM, LM, DH, BH, 1, SL, SL, SLL, F_TRANSB, 1.f, 0.f);
    softmax256_kernel<<<(BH * LM * 32 + 255) / 256, 256>>>(s2, BH * LM);
    // attn3 = softmax(ql @ k^T)   [16,256,4096]
    g128(ql, k, s3, 0, 0, 0, 0, LM, NTOK, DH, BH, SL, SQ, (long long)LM * NTOK, F_TRANSB, 1.f, 0.f);
    softmax_big_kernel<<<BH * LM, 256, NTOK * 4>>>(s3, NTOK / 4);

    // pinv(attn2): z0 = s2^T / (max_row * max_col)
    init_scal_kernel<<<1, 32>>>(scal);
    abs_row_kernel<<<(BH * LM * 32 + 255) / 256, 256>>>(s2, scal);
    abs_col_kernel<<<(BH * LM + 255) / 256, 256>>>(s2, scal);
    zinit_kernel<<<(int)((BH * SLL) / 256), 256>>>(za, s2, scal);

    float* zc = za; float* zn = zb;
    for (int it = 0; it < 6; it++) {
        // xz = s2 @ z
        g64(s2, zc, xz, 0, 0, LM, LM, LM, BH, 1, SLL, SLL, SLL, 0, 1.f, 0.f);
        // u = 7*xz - xz@xz
        g64(xz, xz, t1, 0, xz, LM, LM, LM, BH, 1, SLL, SLL, SLL, F_RES, -1.f, 7.f);
        // v = 15*xz - xz@u
        g64(xz, t1, t2, 0, xz, LM, LM, LM, BH, 1, SLL, SLL, SLL, F_RES, -1.f, 15.f);
        // zn = 3.25*z - 0.25*z@v
        g64(zc, t2, zn, 0, zc, LM, LM, LM, BH, 1, SLL, SLL, SLL, F_RES, -0.25f, 3.25f);
        float* t = zc; zc = zn; zn = t;
    }

    // AV = attn3 @ v   (split-K=8, atomic)
    zero_kernel<<<(BH * LM * DH + 255) / 256, 256>>>(av, (long long)BH * LM * DH);
    g64(s3, v, av, 0, 0, LM, DH, NTOK, BH, 8,
        (long long)LM * NTOK, SQ, SL, F_ATOMIC, 1.f, 0.f);
    // ZAV = pinv @ AV  (split-K=2, atomic)
    zero_kernel<<<(BH * LM * DH + 255) / 256, 256>>>(zav, (long long)BH * LM * DH);
    g64(zc, av, zav, 0, 0, LM, DH, LM, BH, 2, SLL, SL, SL, F_ATOMIC, 1.f, 0.f);
    // out = attn1 @ ZAV
    g64(s1, zav, ao, 0, 0, NTOK, DH, LM, BH, 1,
        (long long)NTOK * LM, SL, SQ, 0, 1.f, 0.f);
    // depthwise conv residual
    conv_add_kernel<<<(int)(((long long)BH * NTOK * DH + 255) / 256), 256>>>(ao, v, res_w);
    // out-proj reading head-major ao directly (merge fused into A-loader), +bias +residual into h
    g128(ao, out_w, h, out_b, h, 0, 0, BATCH * NTOK, DIM, DIM, 1, 0, 0, 0,
         F_TRANSB | F_BIAS | F_RES | F_MERGEA, 1.f, 1.f);
}

extern "C" void kernel_launch(void* const* d_in, const int* in_sizes, int n_in,
                              void* d_out, int out_size)
{
    const float* x        = (const float*)d_in[0];
    const float* fc1_w    = (const float*)d_in[1];
    const float* fc1_b    = (const float*)d_in[2];
    const float* cls_tok  = (const float*)d_in[3];
    const float* l1_nw    = (const float*)d_in[4];
    const float* l1_nb    = (const float*)d_in[5];
    const float* l1_qkv   = (const float*)d_in[6];
    const float* l1_ow    = (const float*)d_in[7];
    const float* l1_ob    = (const float*)d_in[8];
    const float* l1_rw    = (const float*)d_in[9];
    const float* l2_nw    = (const float*)d_in[10];
    const float* l2_nb    = (const float*)d_in[11];
    const float* l2_qkv   = (const float*)d_in[12];
    const float* l2_ow    = (const float*)d_in[13];
    const float* l2_ob    = (const float*)d_in[14];
    const float* l2_rw    = (const float*)d_in[15];
    const float* norm_w   = (const float*)d_in[16];
    const float* norm_b   = (const float*)d_in[17];
    const float* fc2_w    = (const float*)d_in[18];
    const float* fc2_b    = (const float*)d_in[19];
    float* out = (float*)d_out;

    float *h, *xn, *q, *k, *v, *ql, *kl, *s1, *s2, *s3;
    float *za, *zb, *xz, *t1, *t2, *av, *zav, *ao, *clsn, *scal;
    cudaGetSymbolAddress((void**)&h, g_h);
    cudaGetSymbolAddress((void**)&xn, g_xn);
    cudaGetSymbolAddress((void**)&q, g_q);
    cudaGetSymbolAddress((void**)&k, g_k);
    cudaGetSymbolAddress((void**)&v, g_v);
    cudaGetSymbolAddress((void**)&ql, g_ql);
    cudaGetSymbolAddress((void**)&kl, g_kl);
    cudaGetSymbolAddress((void**)&s1, g_s1);
    cudaGetSymbolAddress((void**)&s2, g_s2);
    cudaGetSymbolAddress((void**)&s3, g_s3);
    cudaGetSymbolAddress((void**)&za, g_za);
    cudaGetSymbolAddress((void**)&zb, g_zb);
    cudaGetSymbolAddress((void**)&xz, g_xz);
    cudaGetSymbolAddress((void**)&t1, g_t1);
    cudaGetSymbolAddress((void**)&t2, g_t2);
    cudaGetSymbolAddress((void**)&av, g_av);
    cudaGetSymbolAddress((void**)&zav, g_zav);
    cudaGetSymbolAddress((void**)&ao, g_ao);
    cudaGetSymbolAddress((void**)&clsn, g_clsn);
    cudaGetSymbolAddress((void**)&scal, g_scal);

    // fc1 + relu into rows [1..4095] of each batch
    g128(x, fc1_w, h + DIM, fc1_b, nullptr, nullptr, nullptr, NIN, DIM, LIN, BATCH,
         (long long)NIN * LIN, 0, (long long)NTOK * DIM,
         F_TRANSB | F_RELU | F_BIAS, 1.f, 0.f);
    set_cls_kernel<<<(BATCH * DIM + 255) / 256, 256>>>(h, cls_tok);

    attention_layer(l1_nw, l1_nb, l1_qkv, l1_ow, l1_ob, l1_rw,
                    h, xn, q, k, v, ql, kl, s1, s2, s3,
                    za, zb, xz, t1, t2, av, zav, ao, scal);
    attention_layer(l2_nw, l2_nb, l2_qkv, l2_ow, l2_ob, l2_rw,
                    h, xn, q, k, v, ql, kl, s1, s2, s3,
                    za, zb, xz, t1, t2, av, zav, ao, scal);

    layernorm_kernel<<<BATCH, 256>>>(h, clsn, norm_w, norm_b, (long long)NTOK * DIM, DIM);
    fc2_kernel<<<(BATCH * OUTC + 255) / 256, 256>>>(clsn, fc2_w, fc2_b, out);
}